// round 10
// baseline (speedup 1.0000x reference)
#include <cuda_runtime.h>
#include <math.h>

#define B_SZ   2048
#define INV_TEMP (1.0f/0.07f)
#define MARGIN_C 0.15f

#define FMA2(d,a,b,c) asm("fma.rn.f32x2 %0, %1, %2, %3;" : "=l"(d) : "l"(a), "l"(b), "l"(c))
#define UNPACK2(lo,hi,v) asm("mov.b64 {%0, %1}, %2;" : "=f"(lo), "=f"(hi) : "l"(v))

__device__ float        g_partial[B_SZ];
__device__ unsigned int g_count = 0;
__device__ float        g_dist[64][64];

typedef unsigned long long ull;

// ---- tiny precompute: dist[i][j] = ||pos_i - pos_j|| with zero diagonal ----
__global__ void dist_kernel(const float* __restrict__ cpos)
{
    __shared__ float s_pos[192];
    const int tid = threadIdx.x;          // 256 threads
    if (tid < 192) s_pos[tid] = cpos[tid];
    __syncthreads();
    #pragma unroll
    for (int e = 0; e < 16; ++e) {
        const int idx = tid * 16 + e;
        const int i = idx >> 6, j = idx & 63;
        float dx = s_pos[i*3]   - s_pos[j*3];
        float dy = s_pos[i*3+1] - s_pos[j*3+1];
        float dz = s_pos[i*3+2] - s_pos[j*3+2];
        float d2 = fmaf(dx,dx, fmaf(dy,dy, dz*dz));
        g_dist[i][j] = (i == j) ? 0.0f : sqrtf(d2);
    }
}

__global__ __launch_bounds__(128, 4)
void loss_kernel(const float* __restrict__ pred,
                 const int*   __restrict__ labels,
                 const float* __restrict__ emb,
                 const float* __restrict__ conn,
                 float* __restrict__ out)
{
    __shared__ __align__(16) float s_act_emb[4][1024];   // 16 KB
    __shared__ float s_pred[64];
    __shared__ int   s_lab[64];
    __shared__ int   s_act[4];
    __shared__ int   s_inact[60];
    __shared__ float s_topk;
    __shared__ float s_dot[4][64];
    __shared__ float s_norm[64];
    __shared__ float s_rn[64];
    __shared__ float s_bce[64], s_pl[64], s_sp[64], s_nw[64];
    __shared__ int   s_islast;
    __shared__ float s_red[128];

    const int b   = blockIdx.x;
    const int tid = threadIdx.x;
    const int w   = tid >> 5, lane = tid & 31;

    // ---------------- Phase A (no sync): smem scalars + per-warp act list ----------------
    if (tid < 64) { s_pred[tid] = pred[b*64 + tid]; s_lab[tid] = labels[b*64 + tid]; }

    const int lab0 = labels[b*64 + lane];
    const int lab1 = labels[b*64 + 32 + lane];
    const unsigned m0 = __ballot_sync(0xffffffffu, lab0 != 0);
    const unsigned m1 = __ballot_sync(0xffffffffu, lab1 != 0);
    int act0, act1, act2, act3;
    {
        int a[4]; int na = 0;
        unsigned mm = m0;
        while (mm) { a[na++] = __ffs(mm) - 1; mm &= mm - 1; }
        mm = m1;
        while (mm) { a[na++] = 32 + __ffs(mm) - 1; mm &= mm - 1; }
        act0 = a[0]; act1 = a[1]; act2 = a[2]; act3 = a[3];
    }

    if (w == 0) {
        const unsigned below = (1u << lane) - 1u;
        if (lab0) s_act[__popc(m0 & below)] = lane;
        if (lab1) s_act[__popc(m0) + __popc(m1 & below)] = 32 + lane;
        const unsigned i0 = ~m0, i1 = ~m1;
        if (!lab0) s_inact[__popc(i0 & below)] = lane;
        if (!lab1) s_inact[__popc(i0) + __popc(i1 & below)] = 32 + lane;
    }

    // ---------------- Phase B (no sync before): stage 4 active rows ----------------
    {
        const float4* base = (const float4*)(emb + (size_t)b * 65536);
        ((float4*)s_act_emb[0])[tid]       = base[(size_t)act0 * 256 + tid];
        ((float4*)s_act_emb[0])[tid + 128] = base[(size_t)act0 * 256 + tid + 128];
        ((float4*)s_act_emb[1])[tid]       = base[(size_t)act1 * 256 + tid];
        ((float4*)s_act_emb[1])[tid + 128] = base[(size_t)act1 * 256 + tid + 128];
        ((float4*)s_act_emb[2])[tid]       = base[(size_t)act2 * 256 + tid];
        ((float4*)s_act_emb[2])[tid + 128] = base[(size_t)act2 * 256 + tid + 128];
        ((float4*)s_act_emb[3])[tid]       = base[(size_t)act3 * 256 + tid];
        ((float4*)s_act_emb[3])[tid + 128] = base[(size_t)act3 * 256 + tid + 128];
    }

    // warp 0: parallel top-4 + IoU while Phase B loads are in flight
    if (w == 0) {
        float w0 = pred[b*64 + lane];
        float w1 = pred[b*64 + 32 + lane];
        int inter = 0;
        #pragma unroll
        for (int r = 0; r < 4; ++r) {
            float bv; int bi;
            if (w1 > w0) { bv = w1; bi = lane + 32; } else { bv = w0; bi = lane; }
            #pragma unroll
            for (int off = 16; off; off >>= 1) {
                float ov = __shfl_xor_sync(0xffffffffu, bv, off);
                int   oi = __shfl_xor_sync(0xffffffffu, bi, off);
                if (ov > bv || (ov == bv && oi < bi)) { bv = ov; bi = oi; }
            }
            inter += (bi < 32) ? (int)((m0 >> bi) & 1u) : (int)((m1 >> (bi - 32)) & 1u);
            if (bi == lane)      w0 = -1e30f;
            if (bi == lane + 32) w1 = -1e30f;
        }
        if (lane == 0) {
            float un = (float)(8 - inter);
            s_topk = 1.0f - (float)inter / (un + 1e-8f);
        }
    }
    __syncthreads();

    // ---------------- Phase C: 2 rows/pass, 8 passes/warp, f32x2 FMA ----------------
    {
        const ull zero = 0ull;
        #pragma unroll
        for (int pass = 0; pass < 8; ++pass) {
            const int j0 = w * 16 + pass * 2;
            const ulonglong2* r0 = (const ulonglong2*)(emb + (size_t)b * 65536 + (size_t)j0 * 1024);
            const ulonglong2* r1 = r0 + 256;
            ull d00=zero,d01=zero,d02=zero,d03=zero,n0=zero;
            ull d10=zero,d11=zero,d12=zero,d13=zero,n1=zero;
            #pragma unroll
            for (int ii = 0; ii < 8; ++ii) {
                const int i = lane + ii * 32;
                ulonglong2 e0 = r0[i], e1 = r1[i];
                ulonglong2 a0 = ((const ulonglong2*)s_act_emb[0])[i];
                FMA2(d00,e0.x,a0.x,d00); FMA2(d00,e0.y,a0.y,d00);
                FMA2(d10,e1.x,a0.x,d10); FMA2(d10,e1.y,a0.y,d10);
                ulonglong2 a1 = ((const ulonglong2*)s_act_emb[1])[i];
                FMA2(d01,e0.x,a1.x,d01); FMA2(d01,e0.y,a1.y,d01);
                FMA2(d11,e1.x,a1.x,d11); FMA2(d11,e1.y,a1.y,d11);
                ulonglong2 a2 = ((const ulonglong2*)s_act_emb[2])[i];
                FMA2(d02,e0.x,a2.x,d02); FMA2(d02,e0.y,a2.y,d02);
                FMA2(d12,e1.x,a2.x,d12); FMA2(d12,e1.y,a2.y,d12);
                ulonglong2 a3 = ((const ulonglong2*)s_act_emb[3])[i];
                FMA2(d03,e0.x,a3.x,d03); FMA2(d03,e0.y,a3.y,d03);
                FMA2(d13,e1.x,a3.x,d13); FMA2(d13,e1.y,a3.y,d13);
                FMA2(n0 ,e0.x,e0.x,n0 ); FMA2(n0 ,e0.y,e0.y,n0 );
                FMA2(n1 ,e1.x,e1.x,n1 ); FMA2(n1 ,e1.y,e1.y,n1 );
            }
            float v0,v1,v2,v3,v4,v5,v6,v7,v8,v9;
            { float lo,hi; UNPACK2(lo,hi,d00); v0=lo+hi; }
            { float lo,hi; UNPACK2(lo,hi,d01); v1=lo+hi; }
            { float lo,hi; UNPACK2(lo,hi,d02); v2=lo+hi; }
            { float lo,hi; UNPACK2(lo,hi,d03); v3=lo+hi; }
            { float lo,hi; UNPACK2(lo,hi,n0 ); v4=lo+hi; }
            { float lo,hi; UNPACK2(lo,hi,d10); v5=lo+hi; }
            { float lo,hi; UNPACK2(lo,hi,d11); v6=lo+hi; }
            { float lo,hi; UNPACK2(lo,hi,d12); v7=lo+hi; }
            { float lo,hi; UNPACK2(lo,hi,d13); v8=lo+hi; }
            { float lo,hi; UNPACK2(lo,hi,n1 ); v9=lo+hi; }
            #pragma unroll
            for (int off = 16; off; off >>= 1) {
                v0 += __shfl_down_sync(0xffffffffu, v0, off);
                v1 += __shfl_down_sync(0xffffffffu, v1, off);
                v2 += __shfl_down_sync(0xffffffffu, v2, off);
                v3 += __shfl_down_sync(0xffffffffu, v3, off);
                v4 += __shfl_down_sync(0xffffffffu, v4, off);
                v5 += __shfl_down_sync(0xffffffffu, v5, off);
                v6 += __shfl_down_sync(0xffffffffu, v6, off);
                v7 += __shfl_down_sync(0xffffffffu, v7, off);
                v8 += __shfl_down_sync(0xffffffffu, v8, off);
                v9 += __shfl_down_sync(0xffffffffu, v9, off);
            }
            if (lane == 0) {
                s_dot[0][j0]   = v0; s_dot[1][j0]   = v1;
                s_dot[2][j0]   = v2; s_dot[3][j0]   = v3; s_norm[j0]   = v4;
                s_dot[0][j0+1] = v5; s_dot[1][j0+1] = v6;
                s_dot[2][j0+1] = v7; s_dot[3][j0+1] = v8; s_norm[j0+1] = v9;
            }
        }
    }
    __syncthreads();

    // ---------------- Phase D (warp-parallel) ----------------
    if (tid < 64) {
        s_rn[tid] = 1.0f / fmaxf(sqrtf(s_norm[tid]), 1e-12f);
        const float p   = s_pred[tid];
        const int   lab = s_lab[tid];
        s_bce[tid] = lab ? logf(p) : log1pf(-p);
        s_pl[tid]  = lab ? p : 0.0f;
    }

    // network + spatial: each warp does 16 rows of conn / Dist (L2-resident)
    {
        const float pl0 = s_pred[lane],        pl1 = s_pred[lane + 32];
        const float ml0 = (pl0 > 0.5f) ? 1.0f : 0.0f;
        const float ml1 = (pl1 > 0.5f) ? 1.0f : 0.0f;
        #pragma unroll
        for (int rr = 0; rr < 16; ++rr) {
            const int r = w * 16 + rr;
            float t1 = fmaf(conn[r*64 + lane],   pl0, conn[r*64 + 32 + lane]   * pl1);
            float t2 = fmaf(g_dist[r][lane],     ml0, g_dist[r][lane + 32]     * ml1);
            #pragma unroll
            for (int off = 16; off; off >>= 1) {
                t1 += __shfl_down_sync(0xffffffffu, t1, off);
                t2 += __shfl_down_sync(0xffffffffu, t2, off);
            }
            if (lane == 0) {
                s_nw[r] = t1 * s_pred[r];
                s_sp[r] = t2 * ((s_pred[r] > 0.5f) ? 1.0f : 0.0f);
            }
        }
    }
    __syncthreads();

    // contrastive: 12 pairs in warp 0
    float ce = 0.0f;
    if (tid < 12) {
        const int p  = tid;
        const int k  = p / 3;
        const int jo = p % 3;
        const int col = jo + (jo >= k ? 1 : 0);
        const int ck = s_act[k];
        const int cj = s_act[col];
        const float rk = s_rn[ck];
        const float l0 = s_dot[k][cj] * rk * s_rn[cj] * INV_TEMP;
        const int base = 20 * jo;
        float mx = l0;
        #pragma unroll
        for (int n = 0; n < 20; ++n) {
            int c = s_inact[base + n];
            float vv = s_dot[k][c] * rk * s_rn[c] * INV_TEMP;
            mx = fmaxf(mx, vv);
        }
        float ssum = expf(l0 - mx);
        #pragma unroll
        for (int n = 0; n < 20; ++n) {
            int c = s_inact[base + n];
            float vv = s_dot[k][c] * rk * s_rn[c] * INV_TEMP;
            ssum += expf(vv - mx);
        }
        ce = logf(ssum) + mx - l0;
    }
    if (tid < 32) {
        #pragma unroll
        for (int off = 16; off; off >>= 1) ce += __shfl_down_sync(0xffffffffu, ce, off);
    }

    if (tid < 32) {
        float r_bce = s_bce[tid] + s_bce[tid+32];
        float r_pl  = s_pl [tid] + s_pl [tid+32];
        float r_p   = s_pred[tid] + s_pred[tid+32];
        float r_lab = (float)s_lab[tid] + (float)s_lab[tid+32];
        float r_sp  = s_sp[tid] + s_sp[tid+32];
        float r_nw  = s_nw[tid] + s_nw[tid+32];
        float pm0 = (s_pred[tid] > 0.5f) ? 1.0f : 0.0f;
        float pm1 = (s_pred[tid+32] > 0.5f) ? 1.0f : 0.0f;
        float r_m = pm0 + pm1;
        #pragma unroll
        for (int off = 16; off; off >>= 1) {
            r_bce += __shfl_down_sync(0xffffffffu, r_bce, off);
            r_pl  += __shfl_down_sync(0xffffffffu, r_pl , off);
            r_p   += __shfl_down_sync(0xffffffffu, r_p  , off);
            r_lab += __shfl_down_sync(0xffffffffu, r_lab, off);
            r_sp  += __shfl_down_sync(0xffffffffu, r_sp , off);
            r_nw  += __shfl_down_sync(0xffffffffu, r_nw , off);
            r_m   += __shfl_down_sync(0xffffffffu, r_m  , off);
        }
        if (tid == 0) {
            float score_b    = -r_bce * (1.0f/64.0f);
            float act_mean   = r_pl / r_lab;
            float inact_mean = (r_p - r_pl) / (64.0f - r_lab);
            float margin_b   = fmaxf(MARGIN_C - (act_mean - inact_mean), 0.0f);
            float contr_b    = ce * (1.0f/12.0f);
            float nm         = r_m;
            float spatial_b  = (nm >= 2.0f) ? r_sp / fmaxf(nm*(nm-1.0f), 1.0f) : 0.0f;
            float net_b      = -r_nw * (1.0f/4096.0f);
            g_partial[b] = 3.0f*score_b + 1.0f*margin_b + 2.0f*s_topk
                         + 1.0f*contr_b + 0.5f*spatial_b + 0.5f*net_b;
        }
    }

    // ---------------- fused final reduction (last block) ----------------
    if (tid == 0) {
        __threadfence();
        unsigned int v = atomicAdd(&g_count, 1u);
        s_islast = (v == (unsigned)(B_SZ - 1));
    }
    __syncthreads();
    if (s_islast) {
        float s = 0.0f;
        for (int i = tid; i < B_SZ; i += 128) s += g_partial[i];
        s_red[tid] = s;
        __syncthreads();
        for (int o = 64; o > 0; o >>= 1) {
            if (tid < o) s_red[tid] += s_red[tid + o];
            __syncthreads();
        }
        if (tid == 0) { out[0] = s_red[0] * (1.0f / (float)B_SZ); g_count = 0; }
    }
}

extern "C" void kernel_launch(void* const* d_in, const int* in_sizes, int n_in,
                              void* d_out, int out_size)
{
    const float* pred = (const float*)d_in[0];
    const int*   lab  = (const int*)  d_in[1];
    const float* emb  = (const float*)d_in[2];
    const float* cpos = (const float*)d_in[3];
    const float* conn = (const float*)d_in[4];
    dist_kernel<<<1, 256>>>(cpos);
    loss_kernel<<<B_SZ, 128>>>(pred, lab, emb, conn, (float*)d_out);
}

// round 11
// speedup vs baseline: 1.8853x; 1.8853x over previous
#include <cuda_runtime.h>
#include <math.h>

#define B_SZ   2048
#define INV_TEMP (1.0f/0.07f)
#define MARGIN_C 0.15f
#define DYN_SMEM (16384 + 65536)   // act tiles + 8 warps * 2 * 4KB stream bufs

#define FMA2(d,a,b,c) asm("fma.rn.f32x2 %0, %1, %2, %3;" : "=l"(d) : "l"(a), "l"(b), "l"(c))
#define UNPACK2(lo,hi,v) asm("mov.b64 {%0, %1}, %2;" : "=f"(lo), "=f"(hi) : "l"(v))

__device__ float        g_partial[B_SZ];
__device__ unsigned int g_count = 0;
__device__ float        g_dist[64][64];

typedef unsigned long long ull;

// ---- tiny precompute: dist[i][j] = ||pos_i - pos_j|| with zero diagonal ----
__global__ void dist_kernel(const float* __restrict__ cpos)
{
    __shared__ float s_pos[192];
    const int tid = threadIdx.x;          // 256 threads
    if (tid < 192) s_pos[tid] = cpos[tid];
    __syncthreads();
    #pragma unroll
    for (int e = 0; e < 16; ++e) {
        const int idx = tid * 16 + e;
        const int i = idx >> 6, j = idx & 63;
        float dx = s_pos[i*3]   - s_pos[j*3];
        float dy = s_pos[i*3+1] - s_pos[j*3+1];
        float dz = s_pos[i*3+2] - s_pos[j*3+2];
        float d2 = fmaf(dx,dx, fmaf(dy,dy, dz*dz));
        g_dist[i][j] = (i == j) ? 0.0f : sqrtf(d2);
    }
}

// issue one 4KB row as a cp.async group (128B per lane, 8x16B)
__device__ __forceinline__ void issue_row(unsigned sdst, const float* gsrc, int lane)
{
    #pragma unroll
    for (int c = 0; c < 8; ++c) {
        asm volatile("cp.async.cg.shared.global [%0], [%1], 16;"
                     :: "r"(sdst + c*512 + lane*16), "l"(gsrc + c*128 + lane*4) : "memory");
    }
    asm volatile("cp.async.commit_group;" ::: "memory");
}

__global__ __launch_bounds__(256, 2)
void loss_kernel(const float* __restrict__ pred,
                 const int*   __restrict__ labels,
                 const float* __restrict__ emb,
                 const float* __restrict__ conn,
                 float* __restrict__ out)
{
    extern __shared__ __align__(16) float dyn[];
    float* s_act_emb  = dyn;              // [4][1024], 16 KB
    float* s_stream   = dyn + 4096;       // [8 warps][2][1024], 64 KB

    __shared__ float s_pred[64];
    __shared__ int   s_lab[64];
    __shared__ int   s_act[4];
    __shared__ int   s_inact[60];
    __shared__ float s_topk;
    __shared__ float s_dot[4][64];
    __shared__ float s_norm[64];
    __shared__ float s_rn[64];
    __shared__ float s_bce[64], s_pl[64], s_sp[64], s_nw[64];
    __shared__ int   s_islast;
    __shared__ float s_red[256];

    const int b   = blockIdx.x;
    const int tid = threadIdx.x;
    const int w   = tid >> 5, lane = tid & 31;

    // ---------------- Phase A (no sync): smem scalars + per-warp act list ----------------
    if (tid < 64) { s_pred[tid] = pred[b*64 + tid]; s_lab[tid] = labels[b*64 + tid]; }

    const int lab0 = labels[b*64 + lane];
    const int lab1 = labels[b*64 + 32 + lane];
    const unsigned m0 = __ballot_sync(0xffffffffu, lab0 != 0);
    const unsigned m1 = __ballot_sync(0xffffffffu, lab1 != 0);
    int act0, act1, act2, act3;
    {
        int a[4]; int na = 0;
        unsigned mm = m0;
        while (mm) { a[na++] = __ffs(mm) - 1; mm &= mm - 1; }
        mm = m1;
        while (mm) { a[na++] = 32 + __ffs(mm) - 1; mm &= mm - 1; }
        act0 = a[0]; act1 = a[1]; act2 = a[2]; act3 = a[3];
    }

    if (w == 0) {
        const unsigned below = (1u << lane) - 1u;
        if (lab0) s_act[__popc(m0 & below)] = lane;
        if (lab1) s_act[__popc(m0) + __popc(m1 & below)] = 32 + lane;
        const unsigned i0 = ~m0, i1 = ~m1;
        if (!lab0) s_inact[__popc(i0 & below)] = lane;
        if (!lab1) s_inact[__popc(i0) + __popc(i1 & below)] = 32 + lane;
    }

    // ---------------- Phase B: stage 4 active rows (plain LDG->STS) ----------------
    {
        const float4* base = (const float4*)(emb + (size_t)b * 65536);
        ((float4*)s_act_emb)[tid]       = base[(size_t)act0 * 256 + tid];
        ((float4*)s_act_emb)[tid + 256] = base[(size_t)act1 * 256 + tid];
        ((float4*)s_act_emb)[tid + 512] = base[(size_t)act2 * 256 + tid];
        ((float4*)s_act_emb)[tid + 768] = base[(size_t)act3 * 256 + tid];
    }

    // stream pipeline prologue: 2 rows in flight per warp (no regs held)
    const float* rowbase = emb + (size_t)b * 65536 + (size_t)(w * 8) * 1024;
    unsigned sbuf0;
    {
        unsigned sbase;
        asm("{ .reg .u64 t; cvta.to.shared.u64 t, %1; cvt.u32.u64 %0, t; }"
            : "=r"(sbase) : "l"(s_stream));
        sbuf0 = sbase + (unsigned)(w * 8192);
    }
    issue_row(sbuf0,        rowbase,        lane);
    issue_row(sbuf0 + 4096, rowbase + 1024, lane);

    // warp 0: parallel top-4 + IoU while loads are in flight
    if (w == 0) {
        float w0 = pred[b*64 + lane];
        float w1 = pred[b*64 + 32 + lane];
        int inter = 0;
        #pragma unroll
        for (int r = 0; r < 4; ++r) {
            float bv; int bi;
            if (w1 > w0) { bv = w1; bi = lane + 32; } else { bv = w0; bi = lane; }
            #pragma unroll
            for (int off = 16; off; off >>= 1) {
                float ov = __shfl_xor_sync(0xffffffffu, bv, off);
                int   oi = __shfl_xor_sync(0xffffffffu, bi, off);
                if (ov > bv || (ov == bv && oi < bi)) { bv = ov; bi = oi; }
            }
            inter += (bi < 32) ? (int)((m0 >> bi) & 1u) : (int)((m1 >> (bi - 32)) & 1u);
            if (bi == lane)      w0 = -1e30f;
            if (bi == lane + 32) w1 = -1e30f;
        }
        if (lane == 0) {
            float un = (float)(8 - inter);
            s_topk = 1.0f - (float)inter / (un + 1e-8f);
        }
    }
    __syncthreads();   // act tiles visible to all warps

    // ---------------- Phase C: 8 passes/warp, 1 row/pass, cp.async double buffer ----------------
    {
        const ull zero = 0ull;
        const ulonglong2* acts = (const ulonglong2*)s_act_emb;   // 4 rows x 256 entries
        #pragma unroll
        for (int p = 0; p < 8; ++p) {
            if (p == 7) { asm volatile("cp.async.wait_group 0;" ::: "memory"); }
            else        { asm volatile("cp.async.wait_group 1;" ::: "memory"); }

            const ulonglong2* cur =
                (const ulonglong2*)(s_stream + (size_t)w * 2048 + (size_t)(p & 1) * 1024);
            ull d0=zero,d1=zero,d2=zero,d3=zero,nn=zero;
            #pragma unroll
            for (int ii = 0; ii < 8; ++ii) {
                const int i = lane + ii * 32;
                ulonglong2 e  = cur[i];
                ulonglong2 a0 = acts[i];
                FMA2(d0,e.x,a0.x,d0); FMA2(d0,e.y,a0.y,d0);
                ulonglong2 a1 = acts[i + 256];
                FMA2(d1,e.x,a1.x,d1); FMA2(d1,e.y,a1.y,d1);
                ulonglong2 a2 = acts[i + 512];
                FMA2(d2,e.x,a2.x,d2); FMA2(d2,e.y,a2.y,d2);
                ulonglong2 a3 = acts[i + 768];
                FMA2(d3,e.x,a3.x,d3); FMA2(d3,e.y,a3.y,d3);
                FMA2(nn,e.x,e.x,nn);  FMA2(nn,e.y,e.y,nn);
            }
            // refill the just-consumed buffer (all LDS consumed by FMAs above)
            if (p < 6)
                issue_row(sbuf0 + (unsigned)((p & 1) * 4096), rowbase + (p + 2) * 1024, lane);

            float v0,v1,v2,v3,v4;
            { float lo,hi; UNPACK2(lo,hi,d0); v0=lo+hi; }
            { float lo,hi; UNPACK2(lo,hi,d1); v1=lo+hi; }
            { float lo,hi; UNPACK2(lo,hi,d2); v2=lo+hi; }
            { float lo,hi; UNPACK2(lo,hi,d3); v3=lo+hi; }
            { float lo,hi; UNPACK2(lo,hi,nn); v4=lo+hi; }
            #pragma unroll
            for (int off = 16; off; off >>= 1) {
                v0 += __shfl_down_sync(0xffffffffu, v0, off);
                v1 += __shfl_down_sync(0xffffffffu, v1, off);
                v2 += __shfl_down_sync(0xffffffffu, v2, off);
                v3 += __shfl_down_sync(0xffffffffu, v3, off);
                v4 += __shfl_down_sync(0xffffffffu, v4, off);
            }
            if (lane == 0) {
                const int j = w * 8 + p;
                s_dot[0][j] = v0; s_dot[1][j] = v1;
                s_dot[2][j] = v2; s_dot[3][j] = v3; s_norm[j] = v4;
            }
        }
    }
    __syncthreads();

    // ---------------- Phase D (warp-parallel) ----------------
    if (tid < 64) {
        s_rn[tid] = 1.0f / fmaxf(sqrtf(s_norm[tid]), 1e-12f);
        const float p   = s_pred[tid];
        const int   lab = s_lab[tid];
        s_bce[tid] = lab ? logf(p) : log1pf(-p);
        s_pl[tid]  = lab ? p : 0.0f;
    }

    // network + spatial: each warp does 8 rows of conn / Dist (L2-resident)
    {
        const float pl0 = s_pred[lane],        pl1 = s_pred[lane + 32];
        const float ml0 = (pl0 > 0.5f) ? 1.0f : 0.0f;
        const float ml1 = (pl1 > 0.5f) ? 1.0f : 0.0f;
        #pragma unroll
        for (int rr = 0; rr < 8; ++rr) {
            const int r = w * 8 + rr;
            float t1 = fmaf(conn[r*64 + lane],   pl0, conn[r*64 + 32 + lane]   * pl1);
            float t2 = fmaf(g_dist[r][lane],     ml0, g_dist[r][lane + 32]     * ml1);
            #pragma unroll
            for (int off = 16; off; off >>= 1) {
                t1 += __shfl_down_sync(0xffffffffu, t1, off);
                t2 += __shfl_down_sync(0xffffffffu, t2, off);
            }
            if (lane == 0) {
                s_nw[r] = t1 * s_pred[r];
                s_sp[r] = t2 * ((s_pred[r] > 0.5f) ? 1.0f : 0.0f);
            }
        }
    }
    __syncthreads();

    // contrastive: 12 pairs in warp 0
    float ce = 0.0f;
    if (tid < 12) {
        const int p  = tid;
        const int k  = p / 3;
        const int jo = p % 3;
        const int col = jo + (jo >= k ? 1 : 0);
        const int ck = s_act[k];
        const int cj = s_act[col];
        const float rk = s_rn[ck];
        const float l0 = s_dot[k][cj] * rk * s_rn[cj] * INV_TEMP;
        const int base = 20 * jo;
        float mx = l0;
        #pragma unroll
        for (int n = 0; n < 20; ++n) {
            int c = s_inact[base + n];
            float vv = s_dot[k][c] * rk * s_rn[c] * INV_TEMP;
            mx = fmaxf(mx, vv);
        }
        float ssum = expf(l0 - mx);
        #pragma unroll
        for (int n = 0; n < 20; ++n) {
            int c = s_inact[base + n];
            float vv = s_dot[k][c] * rk * s_rn[c] * INV_TEMP;
            ssum += expf(vv - mx);
        }
        ce = logf(ssum) + mx - l0;
    }
    if (tid < 32) {
        #pragma unroll
        for (int off = 16; off; off >>= 1) ce += __shfl_down_sync(0xffffffffu, ce, off);
    }

    if (tid < 32) {
        float r_bce = s_bce[tid] + s_bce[tid+32];
        float r_pl  = s_pl [tid] + s_pl [tid+32];
        float r_p   = s_pred[tid] + s_pred[tid+32];
        float r_lab = (float)s_lab[tid] + (float)s_lab[tid+32];
        float r_sp  = s_sp[tid] + s_sp[tid+32];
        float r_nw  = s_nw[tid] + s_nw[tid+32];
        float pm0 = (s_pred[tid] > 0.5f) ? 1.0f : 0.0f;
        float pm1 = (s_pred[tid+32] > 0.5f) ? 1.0f : 0.0f;
        float r_m = pm0 + pm1;
        #pragma unroll
        for (int off = 16; off; off >>= 1) {
            r_bce += __shfl_down_sync(0xffffffffu, r_bce, off);
            r_pl  += __shfl_down_sync(0xffffffffu, r_pl , off);
            r_p   += __shfl_down_sync(0xffffffffu, r_p  , off);
            r_lab += __shfl_down_sync(0xffffffffu, r_lab, off);
            r_sp  += __shfl_down_sync(0xffffffffu, r_sp , off);
            r_nw  += __shfl_down_sync(0xffffffffu, r_nw , off);
            r_m   += __shfl_down_sync(0xffffffffu, r_m  , off);
        }
        if (tid == 0) {
            float score_b    = -r_bce * (1.0f/64.0f);
            float act_mean   = r_pl / r_lab;
            float inact_mean = (r_p - r_pl) / (64.0f - r_lab);
            float margin_b   = fmaxf(MARGIN_C - (act_mean - inact_mean), 0.0f);
            float contr_b    = ce * (1.0f/12.0f);
            float nm         = r_m;
            float spatial_b  = (nm >= 2.0f) ? r_sp / fmaxf(nm*(nm-1.0f), 1.0f) : 0.0f;
            float net_b      = -r_nw * (1.0f/4096.0f);
            g_partial[b] = 3.0f*score_b + 1.0f*margin_b + 2.0f*s_topk
                         + 1.0f*contr_b + 0.5f*spatial_b + 0.5f*net_b;
        }
    }

    // ---------------- fused final reduction (last block) ----------------
    if (tid == 0) {
        __threadfence();
        unsigned int v = atomicAdd(&g_count, 1u);
        s_islast = (v == (unsigned)(B_SZ - 1));
    }
    __syncthreads();
    if (s_islast) {
        float s = 0.0f;
        for (int i = tid; i < B_SZ; i += 256) s += g_partial[i];
        s_red[tid] = s;
        __syncthreads();
        for (int o = 128; o > 0; o >>= 1) {
            if (tid < o) s_red[tid] += s_red[tid + o];
            __syncthreads();
        }
        if (tid == 0) { out[0] = s_red[0] * (1.0f / (float)B_SZ); g_count = 0; }
    }
}

extern "C" void kernel_launch(void* const* d_in, const int* in_sizes, int n_in,
                              void* d_out, int out_size)
{
    const float* pred = (const float*)d_in[0];
    const int*   lab  = (const int*)  d_in[1];
    const float* emb  = (const float*)d_in[2];
    const float* cpos = (const float*)d_in[3];
    const float* conn = (const float*)d_in[4];
    static int attr_done = 0;
    if (!attr_done) {
        cudaFuncSetAttribute(loss_kernel,
                             cudaFuncAttributeMaxDynamicSharedMemorySize, DYN_SMEM);
        attr_done = 1;
    }
    dist_kernel<<<1, 256>>>(cpos);
    loss_kernel<<<B_SZ, 256, DYN_SMEM>>>(pred, lab, emb, conn, (float*)d_out);
}

// round 12
// speedup vs baseline: 1.9679x; 1.0438x over previous
#include <cuda_runtime.h>
#include <math.h>

#define B_SZ   2048
#define INV_TEMP (1.0f/0.07f)
#define MARGIN_C 0.15f
#define DYN_SMEM (16384 + 4*3*4096)   // act tiles + 4 warps * 3 * 4KB stream bufs = 64KB

#define FMA2(d,a,b,c) asm("fma.rn.f32x2 %0, %1, %2, %3;" : "=l"(d) : "l"(a), "l"(b), "l"(c))
#define UNPACK2(lo,hi,v) asm("mov.b64 {%0, %1}, %2;" : "=f"(lo), "=f"(hi) : "l"(v))

__device__ float        g_partial[B_SZ];
__device__ unsigned int g_count = 0;
__device__ float        g_dist[64][64];

typedef unsigned long long ull;

// ---- tiny precompute: dist[i][j] = ||pos_i - pos_j|| with zero diagonal ----
__global__ void dist_kernel(const float* __restrict__ cpos)
{
    __shared__ float s_pos[192];
    const int tid = threadIdx.x;          // 256 threads
    if (tid < 192) s_pos[tid] = cpos[tid];
    __syncthreads();
    #pragma unroll
    for (int e = 0; e < 16; ++e) {
        const int idx = tid * 16 + e;
        const int i = idx >> 6, j = idx & 63;
        float dx = s_pos[i*3]   - s_pos[j*3];
        float dy = s_pos[i*3+1] - s_pos[j*3+1];
        float dz = s_pos[i*3+2] - s_pos[j*3+2];
        float d2 = fmaf(dx,dx, fmaf(dy,dy, dz*dz));
        g_dist[i][j] = (i == j) ? 0.0f : sqrtf(d2);
    }
}

// issue one 4KB row as a cp.async group (128B per lane, 8x16B)
__device__ __forceinline__ void issue_row(unsigned sdst, const float* gsrc, int lane)
{
    #pragma unroll
    for (int c = 0; c < 8; ++c) {
        asm volatile("cp.async.cg.shared.global [%0], [%1], 16;"
                     :: "r"(sdst + c*512 + lane*16), "l"(gsrc + c*128 + lane*4) : "memory");
    }
    asm volatile("cp.async.commit_group;" ::: "memory");
}

__global__ __launch_bounds__(128, 3)
void loss_kernel(const float* __restrict__ pred,
                 const int*   __restrict__ labels,
                 const float* __restrict__ emb,
                 const float* __restrict__ conn,
                 float* __restrict__ out)
{
    extern __shared__ __align__(16) float dyn[];
    float* s_act_emb  = dyn;              // [4][1024], 16 KB
    float* s_stream   = dyn + 4096;       // [4 warps][3][1024], 48 KB

    __shared__ float s_pred[64];
    __shared__ int   s_lab[64];
    __shared__ int   s_act[4];
    __shared__ int   s_inact[60];
    __shared__ float s_topk;
    __shared__ float s_dot[4][64];
    __shared__ float s_norm[64];
    __shared__ float s_rn[64];
    __shared__ float s_bce[64], s_pl[64], s_sp[64], s_nw[64];
    __shared__ int   s_islast;
    __shared__ float s_red[128];

    const int b   = blockIdx.x;
    const int tid = threadIdx.x;
    const int w   = tid >> 5, lane = tid & 31;

    // ---------------- Phase A (no sync): smem scalars + per-warp act list ----------------
    if (tid < 64) { s_pred[tid] = pred[b*64 + tid]; s_lab[tid] = labels[b*64 + tid]; }

    const int lab0 = labels[b*64 + lane];
    const int lab1 = labels[b*64 + 32 + lane];
    const unsigned m0 = __ballot_sync(0xffffffffu, lab0 != 0);
    const unsigned m1 = __ballot_sync(0xffffffffu, lab1 != 0);
    int act0, act1, act2, act3;
    {
        int a[4]; int na = 0;
        unsigned mm = m0;
        while (mm) { a[na++] = __ffs(mm) - 1; mm &= mm - 1; }
        mm = m1;
        while (mm) { a[na++] = 32 + __ffs(mm) - 1; mm &= mm - 1; }
        act0 = a[0]; act1 = a[1]; act2 = a[2]; act3 = a[3];
    }

    if (w == 0) {
        const unsigned below = (1u << lane) - 1u;
        if (lab0) s_act[__popc(m0 & below)] = lane;
        if (lab1) s_act[__popc(m0) + __popc(m1 & below)] = 32 + lane;
        const unsigned i0 = ~m0, i1 = ~m1;
        if (!lab0) s_inact[__popc(i0 & below)] = lane;
        if (!lab1) s_inact[__popc(i0) + __popc(i1 & below)] = 32 + lane;
    }

    // ---------------- Phase B: stage 4 active rows (plain LDG->STS) ----------------
    {
        const float4* base = (const float4*)(emb + (size_t)b * 65536);
        #pragma unroll
        for (int q = 0; q < 2; ++q) {
            ((float4*)s_act_emb)[tid + q*128]       = base[(size_t)act0 * 256 + tid + q*128];
            ((float4*)s_act_emb)[tid + q*128 + 256] = base[(size_t)act1 * 256 + tid + q*128];
            ((float4*)s_act_emb)[tid + q*128 + 512] = base[(size_t)act2 * 256 + tid + q*128];
            ((float4*)s_act_emb)[tid + q*128 + 768] = base[(size_t)act3 * 256 + tid + q*128];
        }
    }

    // stream pipeline prologue: rows 0,1,2 of this warp's 16 in flight
    const float* rowbase = emb + (size_t)b * 65536 + (size_t)(w * 16) * 1024;
    unsigned sbuf0;
    {
        unsigned sbase;
        asm("{ .reg .u64 t; cvta.to.shared.u64 t, %1; cvt.u32.u64 %0, t; }"
            : "=r"(sbase) : "l"(s_stream));
        sbuf0 = sbase + (unsigned)(w * 12288);
    }
    issue_row(sbuf0,        rowbase,        lane);
    issue_row(sbuf0 + 4096, rowbase + 1024, lane);
    issue_row(sbuf0 + 8192, rowbase + 2048, lane);

    // warp 0: parallel top-4 + IoU while loads are in flight
    if (w == 0) {
        float w0 = pred[b*64 + lane];
        float w1 = pred[b*64 + 32 + lane];
        int inter = 0;
        #pragma unroll
        for (int r = 0; r < 4; ++r) {
            float bv; int bi;
            if (w1 > w0) { bv = w1; bi = lane + 32; } else { bv = w0; bi = lane; }
            #pragma unroll
            for (int off = 16; off; off >>= 1) {
                float ov = __shfl_xor_sync(0xffffffffu, bv, off);
                int   oi = __shfl_xor_sync(0xffffffffu, bi, off);
                if (ov > bv || (ov == bv && oi < bi)) { bv = ov; bi = oi; }
            }
            inter += (bi < 32) ? (int)((m0 >> bi) & 1u) : (int)((m1 >> (bi - 32)) & 1u);
            if (bi == lane)      w0 = -1e30f;
            if (bi == lane + 32) w1 = -1e30f;
        }
        if (lane == 0) {
            float un = (float)(8 - inter);
            s_topk = 1.0f - (float)inter / (un + 1e-8f);
        }
    }
    __syncthreads();   // act tiles visible to all warps

    // ---------- Phase C: 8 passes/warp, 2 rows/pass, 3-buffer cp.async pipeline ----------
    {
        const ull zero = 0ull;
        const ulonglong2* acts = (const ulonglong2*)s_act_emb;   // 4 rows x 256 entries
        #pragma unroll
        for (int p = 0; p < 8; ++p) {
            if (p == 7) { asm volatile("cp.async.wait_group 0;" ::: "memory"); }
            else        { asm volatile("cp.async.wait_group 1;" ::: "memory"); }

            const int b0i = (2*p) % 3, b1i = (2*p + 1) % 3;
            const ulonglong2* cur0 =
                (const ulonglong2*)(s_stream + (size_t)w * 3072 + (size_t)b0i * 1024);
            const ulonglong2* cur1 =
                (const ulonglong2*)(s_stream + (size_t)w * 3072 + (size_t)b1i * 1024);

            ull d00=zero,d01=zero,d02=zero,d03=zero,n0=zero;
            ull d10=zero,d11=zero,d12=zero,d13=zero,n1=zero;
            #pragma unroll
            for (int ii = 0; ii < 8; ++ii) {
                const int i = lane + ii * 32;
                ulonglong2 e0 = cur0[i], e1 = cur1[i];
                ulonglong2 a0 = acts[i];
                FMA2(d00,e0.x,a0.x,d00); FMA2(d00,e0.y,a0.y,d00);
                FMA2(d10,e1.x,a0.x,d10); FMA2(d10,e1.y,a0.y,d10);
                ulonglong2 a1 = acts[i + 256];
                FMA2(d01,e0.x,a1.x,d01); FMA2(d01,e0.y,a1.y,d01);
                FMA2(d11,e1.x,a1.x,d11); FMA2(d11,e1.y,a1.y,d11);
                ulonglong2 a2 = acts[i + 512];
                FMA2(d02,e0.x,a2.x,d02); FMA2(d02,e0.y,a2.y,d02);
                FMA2(d12,e1.x,a2.x,d12); FMA2(d12,e1.y,a2.y,d12);
                ulonglong2 a3 = acts[i + 768];
                FMA2(d03,e0.x,a3.x,d03); FMA2(d03,e0.y,a3.y,d03);
                FMA2(d13,e1.x,a3.x,d13); FMA2(d13,e1.y,a3.y,d13);
                FMA2(n0 ,e0.x,e0.x,n0 ); FMA2(n0 ,e0.y,e0.y,n0 );
                FMA2(n1 ,e1.x,e1.x,n1 ); FMA2(n1 ,e1.y,e1.y,n1 );
            }

            // refill the two buffers just consumed (rows 2p+3 -> b0i, 2p+4 -> b1i)
            {
                const int r3 = 2*p + 3, r4 = 2*p + 4;
                if (r3 < 16) issue_row(sbuf0 + (unsigned)(b0i * 4096), rowbase + r3 * 1024, lane);
                if (r4 < 16) issue_row(sbuf0 + (unsigned)(b1i * 4096), rowbase + r4 * 1024, lane);
            }

            float v0,v1,v2,v3,v4,v5,v6,v7,v8,v9;
            { float lo,hi; UNPACK2(lo,hi,d00); v0=lo+hi; }
            { float lo,hi; UNPACK2(lo,hi,d01); v1=lo+hi; }
            { float lo,hi; UNPACK2(lo,hi,d02); v2=lo+hi; }
            { float lo,hi; UNPACK2(lo,hi,d03); v3=lo+hi; }
            { float lo,hi; UNPACK2(lo,hi,n0 ); v4=lo+hi; }
            { float lo,hi; UNPACK2(lo,hi,d10); v5=lo+hi; }
            { float lo,hi; UNPACK2(lo,hi,d11); v6=lo+hi; }
            { float lo,hi; UNPACK2(lo,hi,d12); v7=lo+hi; }
            { float lo,hi; UNPACK2(lo,hi,d13); v8=lo+hi; }
            { float lo,hi; UNPACK2(lo,hi,n1 ); v9=lo+hi; }
            #pragma unroll
            for (int off = 16; off; off >>= 1) {
                v0 += __shfl_down_sync(0xffffffffu, v0, off);
                v1 += __shfl_down_sync(0xffffffffu, v1, off);
                v2 += __shfl_down_sync(0xffffffffu, v2, off);
                v3 += __shfl_down_sync(0xffffffffu, v3, off);
                v4 += __shfl_down_sync(0xffffffffu, v4, off);
                v5 += __shfl_down_sync(0xffffffffu, v5, off);
                v6 += __shfl_down_sync(0xffffffffu, v6, off);
                v7 += __shfl_down_sync(0xffffffffu, v7, off);
                v8 += __shfl_down_sync(0xffffffffu, v8, off);
                v9 += __shfl_down_sync(0xffffffffu, v9, off);
            }
            if (lane == 0) {
                const int j0 = w * 16 + 2*p;
                s_dot[0][j0]   = v0; s_dot[1][j0]   = v1;
                s_dot[2][j0]   = v2; s_dot[3][j0]   = v3; s_norm[j0]   = v4;
                s_dot[0][j0+1] = v5; s_dot[1][j0+1] = v6;
                s_dot[2][j0+1] = v7; s_dot[3][j0+1] = v8; s_norm[j0+1] = v9;
            }
        }
    }
    __syncthreads();

    // ---------------- Phase D (warp-parallel) ----------------
    if (tid < 64) {
        s_rn[tid] = 1.0f / fmaxf(sqrtf(s_norm[tid]), 1e-12f);
        const float p   = s_pred[tid];
        const int   lab = s_lab[tid];
        s_bce[tid] = lab ? logf(p) : log1pf(-p);
        s_pl[tid]  = lab ? p : 0.0f;
    }

    // network + spatial: each warp does 16 rows of conn / Dist (L2-resident)
    {
        const float pl0 = s_pred[lane],        pl1 = s_pred[lane + 32];
        const float ml0 = (pl0 > 0.5f) ? 1.0f : 0.0f;
        const float ml1 = (pl1 > 0.5f) ? 1.0f : 0.0f;
        #pragma unroll
        for (int rr = 0; rr < 16; ++rr) {
            const int r = w * 16 + rr;
            float t1 = fmaf(conn[r*64 + lane],   pl0, conn[r*64 + 32 + lane]   * pl1);
            float t2 = fmaf(g_dist[r][lane],     ml0, g_dist[r][lane + 32]     * ml1);
            #pragma unroll
            for (int off = 16; off; off >>= 1) {
                t1 += __shfl_down_sync(0xffffffffu, t1, off);
                t2 += __shfl_down_sync(0xffffffffu, t2, off);
            }
            if (lane == 0) {
                s_nw[r] = t1 * s_pred[r];
                s_sp[r] = t2 * ((s_pred[r] > 0.5f) ? 1.0f : 0.0f);
            }
        }
    }
    __syncthreads();

    // contrastive: 12 pairs in warp 0
    float ce = 0.0f;
    if (tid < 12) {
        const int p  = tid;
        const int k  = p / 3;
        const int jo = p % 3;
        const int col = jo + (jo >= k ? 1 : 0);
        const int ck = s_act[k];
        const int cj = s_act[col];
        const float rk = s_rn[ck];
        const float l0 = s_dot[k][cj] * rk * s_rn[cj] * INV_TEMP;
        const int base = 20 * jo;
        float mx = l0;
        #pragma unroll
        for (int n = 0; n < 20; ++n) {
            int c = s_inact[base + n];
            float vv = s_dot[k][c] * rk * s_rn[c] * INV_TEMP;
            mx = fmaxf(mx, vv);
        }
        float ssum = expf(l0 - mx);
        #pragma unroll
        for (int n = 0; n < 20; ++n) {
            int c = s_inact[base + n];
            float vv = s_dot[k][c] * rk * s_rn[c] * INV_TEMP;
            ssum += expf(vv - mx);
        }
        ce = logf(ssum) + mx - l0;
    }
    if (tid < 32) {
        #pragma unroll
        for (int off = 16; off; off >>= 1) ce += __shfl_down_sync(0xffffffffu, ce, off);
    }

    if (tid < 32) {
        float r_bce = s_bce[tid] + s_bce[tid+32];
        float r_pl  = s_pl [tid] + s_pl [tid+32];
        float r_p   = s_pred[tid] + s_pred[tid+32];
        float r_lab = (float)s_lab[tid] + (float)s_lab[tid+32];
        float r_sp  = s_sp[tid] + s_sp[tid+32];
        float r_nw  = s_nw[tid] + s_nw[tid+32];
        float pm0 = (s_pred[tid] > 0.5f) ? 1.0f : 0.0f;
        float pm1 = (s_pred[tid+32] > 0.5f) ? 1.0f : 0.0f;
        float r_m = pm0 + pm1;
        #pragma unroll
        for (int off = 16; off; off >>= 1) {
            r_bce += __shfl_down_sync(0xffffffffu, r_bce, off);
            r_pl  += __shfl_down_sync(0xffffffffu, r_pl , off);
            r_p   += __shfl_down_sync(0xffffffffu, r_p  , off);
            r_lab += __shfl_down_sync(0xffffffffu, r_lab, off);
            r_sp  += __shfl_down_sync(0xffffffffu, r_sp , off);
            r_nw  += __shfl_down_sync(0xffffffffu, r_nw , off);
            r_m   += __shfl_down_sync(0xffffffffu, r_m  , off);
        }
        if (tid == 0) {
            float score_b    = -r_bce * (1.0f/64.0f);
            float act_mean   = r_pl / r_lab;
            float inact_mean = (r_p - r_pl) / (64.0f - r_lab);
            float margin_b   = fmaxf(MARGIN_C - (act_mean - inact_mean), 0.0f);
            float contr_b    = ce * (1.0f/12.0f);
            float nm         = r_m;
            float spatial_b  = (nm >= 2.0f) ? r_sp / fmaxf(nm*(nm-1.0f), 1.0f) : 0.0f;
            float net_b      = -r_nw * (1.0f/4096.0f);
            g_partial[b] = 3.0f*score_b + 1.0f*margin_b + 2.0f*s_topk
                         + 1.0f*contr_b + 0.5f*spatial_b + 0.5f*net_b;
        }
    }

    // ---------------- fused final reduction (last block) ----------------
    if (tid == 0) {
        __threadfence();
        unsigned int v = atomicAdd(&g_count, 1u);
        s_islast = (v == (unsigned)(B_SZ - 1));
    }
    __syncthreads();
    if (s_islast) {
        float s = 0.0f;
        for (int i = tid; i < B_SZ; i += 128) s += g_partial[i];
        s_red[tid] = s;
        __syncthreads();
        for (int o = 64; o > 0; o >>= 1) {
            if (tid < o) s_red[tid] += s_red[tid + o];
            __syncthreads();
        }
        if (tid == 0) { out[0] = s_red[0] * (1.0f / (float)B_SZ); g_count = 0; }
    }
}

extern "C" void kernel_launch(void* const* d_in, const int* in_sizes, int n_in,
                              void* d_out, int out_size)
{
    const float* pred = (const float*)d_in[0];
    const int*   lab  = (const int*)  d_in[1];
    const float* emb  = (const float*)d_in[2];
    const float* cpos = (const float*)d_in[3];
    const float* conn = (const float*)d_in[4];
    static int attr_done = 0;
    if (!attr_done) {
        cudaFuncSetAttribute(loss_kernel,
                             cudaFuncAttributeMaxDynamicSharedMemorySize, DYN_SMEM);
        attr_done = 1;
    }
    dist_kernel<<<1, 256>>>(cpos);
    loss_kernel<<<B_SZ, 128, DYN_SMEM>>>(pred, lab, emb, conn, (float*)d_out);
}

// round 13
// speedup vs baseline: 2.0872x; 1.0606x over previous
#include <cuda_runtime.h>
#include <math.h>

#define B_SZ   2048
#define INV_TEMP (1.0f/0.07f)
#define MARGIN_C 0.15f
// act tiles (16KB) + 8 warps * 5 * 2KB chunk ring (80KB)
#define DYN_SMEM (16384 + 8*5*2048)

#define FMA2(d,a,b,c) asm("fma.rn.f32x2 %0, %1, %2, %3;" : "=l"(d) : "l"(a), "l"(b), "l"(c))
#define UNPACK2(lo,hi,v) asm("mov.b64 {%0, %1}, %2;" : "=f"(lo), "=f"(hi) : "l"(v))

__device__ float        g_partial[B_SZ];
__device__ unsigned int g_count = 0;
__device__ float        g_dist[64][64];

typedef unsigned long long ull;

// ---- tiny precompute: dist[i][j] = ||pos_i - pos_j|| with zero diagonal ----
__global__ void dist_kernel(const float* __restrict__ cpos)
{
    __shared__ float s_pos[192];
    const int tid = threadIdx.x;          // 256 threads
    if (tid < 192) s_pos[tid] = cpos[tid];
    __syncthreads();
    #pragma unroll
    for (int e = 0; e < 16; ++e) {
        const int idx = tid * 16 + e;
        const int i = idx >> 6, j = idx & 63;
        float dx = s_pos[i*3]   - s_pos[j*3];
        float dy = s_pos[i*3+1] - s_pos[j*3+1];
        float dz = s_pos[i*3+2] - s_pos[j*3+2];
        float d2 = fmaf(dx,dx, fmaf(dy,dy, dz*dz));
        g_dist[i][j] = (i == j) ? 0.0f : sqrtf(d2);
    }
}

// issue one 2KB half-row chunk as a cp.async group (64B per lane, 4x16B)
__device__ __forceinline__ void issue_chunk(unsigned sdst, const float* gsrc, int lane)
{
    #pragma unroll
    for (int c = 0; c < 4; ++c) {
        asm volatile("cp.async.cg.shared.global [%0], [%1], 16;"
                     :: "r"(sdst + c*512 + lane*16), "l"(gsrc + c*128 + lane*4) : "memory");
    }
    asm volatile("cp.async.commit_group;" ::: "memory");
}

// chunk c (0..15, per warp): pass p=c>>2, sub=c&3 -> row 2p+(sub&1), half sub>>1
__device__ __forceinline__ int chunk_src_off(int c)
{
    const int row = ((c >> 2) << 1) + (c & 1);
    const int h   = (c >> 1) & 1;
    return row * 1024 + h * 512;
}

__global__ __launch_bounds__(256, 2)
void loss_kernel(const float* __restrict__ pred,
                 const int*   __restrict__ labels,
                 const float* __restrict__ emb,
                 const float* __restrict__ conn,
                 float* __restrict__ out)
{
    extern __shared__ __align__(16) float dyn[];
    float* s_act_emb  = dyn;              // [4][1024], 16 KB
    float* s_stream   = dyn + 4096;       // [8 warps][5][512 floats], 80 KB

    __shared__ float s_pred[64];
    __shared__ int   s_lab[64];
    __shared__ int   s_act[4];
    __shared__ int   s_inact[60];
    __shared__ float s_topk;
    __shared__ float s_dot[4][64];
    __shared__ float s_norm[64];
    __shared__ float s_rn[64];
    __shared__ float s_bce[64], s_pl[64], s_sp[64], s_nw[64];
    __shared__ int   s_islast;
    __shared__ float s_red[256];

    const int b   = blockIdx.x;
    const int tid = threadIdx.x;
    const int w   = tid >> 5, lane = tid & 31;

    // ---------------- Phase A (no sync): smem scalars + per-warp act list ----------------
    if (tid < 64) { s_pred[tid] = pred[b*64 + tid]; s_lab[tid] = labels[b*64 + tid]; }

    const int lab0 = labels[b*64 + lane];
    const int lab1 = labels[b*64 + 32 + lane];
    const unsigned m0 = __ballot_sync(0xffffffffu, lab0 != 0);
    const unsigned m1 = __ballot_sync(0xffffffffu, lab1 != 0);
    int act0, act1, act2, act3;
    {
        int a[4]; int na = 0;
        unsigned mm = m0;
        while (mm) { a[na++] = __ffs(mm) - 1; mm &= mm - 1; }
        mm = m1;
        while (mm) { a[na++] = 32 + __ffs(mm) - 1; mm &= mm - 1; }
        act0 = a[0]; act1 = a[1]; act2 = a[2]; act3 = a[3];
    }

    if (w == 0) {
        const unsigned below = (1u << lane) - 1u;
        if (lab0) s_act[__popc(m0 & below)] = lane;
        if (lab1) s_act[__popc(m0) + __popc(m1 & below)] = 32 + lane;
        const unsigned i0 = ~m0, i1 = ~m1;
        if (!lab0) s_inact[__popc(i0 & below)] = lane;
        if (!lab1) s_inact[__popc(i0) + __popc(i1 & below)] = 32 + lane;
    }

    // ---------------- Phase B: stage 4 active rows (plain LDG->STS) ----------------
    {
        const float4* base = (const float4*)(emb + (size_t)b * 65536);
        ((float4*)s_act_emb)[tid]       = base[(size_t)act0 * 256 + tid];
        ((float4*)s_act_emb)[tid + 256] = base[(size_t)act1 * 256 + tid];
        ((float4*)s_act_emb)[tid + 512] = base[(size_t)act2 * 256 + tid];
        ((float4*)s_act_emb)[tid + 768] = base[(size_t)act3 * 256 + tid];
    }

    // stream pipeline prologue: chunks 0..3 of this warp's 8 rows in flight
    const float* rowbase = emb + (size_t)b * 65536 + (size_t)(w * 8) * 1024;
    unsigned sbuf0;
    {
        unsigned sbase;
        asm("{ .reg .u64 t; cvta.to.shared.u64 t, %1; cvt.u32.u64 %0, t; }"
            : "=r"(sbase) : "l"(s_stream));
        sbuf0 = sbase + (unsigned)(w * 10240);
    }
    issue_chunk(sbuf0 + 0*2048, rowbase + chunk_src_off(0), lane);
    issue_chunk(sbuf0 + 1*2048, rowbase + chunk_src_off(1), lane);
    issue_chunk(sbuf0 + 2*2048, rowbase + chunk_src_off(2), lane);
    issue_chunk(sbuf0 + 3*2048, rowbase + chunk_src_off(3), lane);

    // warp 0: parallel top-4 + IoU while loads are in flight
    if (w == 0) {
        float w0 = pred[b*64 + lane];
        float w1 = pred[b*64 + 32 + lane];
        int inter = 0;
        #pragma unroll
        for (int r = 0; r < 4; ++r) {
            float bv; int bi;
            if (w1 > w0) { bv = w1; bi = lane + 32; } else { bv = w0; bi = lane; }
            #pragma unroll
            for (int off = 16; off; off >>= 1) {
                float ov = __shfl_xor_sync(0xffffffffu, bv, off);
                int   oi = __shfl_xor_sync(0xffffffffu, bi, off);
                if (ov > bv || (ov == bv && oi < bi)) { bv = ov; bi = oi; }
            }
            inter += (bi < 32) ? (int)((m0 >> bi) & 1u) : (int)((m1 >> (bi - 32)) & 1u);
            if (bi == lane)      w0 = -1e30f;
            if (bi == lane + 32) w1 = -1e30f;
        }
        if (lane == 0) {
            float un = (float)(8 - inter);
            s_topk = 1.0f - (float)inter / (un + 1e-8f);
        }
    }
    __syncthreads();   // act tiles visible to all warps

    // ---- Phase C: 4 passes x 2 rows, 2 half-passes each, 5-chunk cp.async ring ----
    {
        const ull zero = 0ull;
        const ulonglong2* acts = (const ulonglong2*)s_act_emb;   // 4 rows x 256 ull2
        #pragma unroll
        for (int p = 0; p < 4; ++p) {
            ull d00=zero,d01=zero,d02=zero,d03=zero,n0=zero;
            ull d10=zero,d11=zero,d12=zero,d13=zero,n1=zero;
            #pragma unroll
            for (int h = 0; h < 2; ++h) {
                const int q = 2*p + h;                 // halfpass 0..7
                if (q == 7) { asm volatile("cp.async.wait_group 0;" ::: "memory"); }
                else        { asm volatile("cp.async.wait_group 2;" ::: "memory"); }

                const int c0 = 4*p + 2*h, c1 = c0 + 1; // chunks: rows 2p,2p+1 half h
                const ulonglong2* cur0 =
                    (const ulonglong2*)(s_stream + (size_t)w * 2560 + (size_t)(c0 % 5) * 512);
                const ulonglong2* cur1 =
                    (const ulonglong2*)(s_stream + (size_t)w * 2560 + (size_t)(c1 % 5) * 512);
                const int abase = h * 128;

                #pragma unroll
                for (int ii = 0; ii < 4; ++ii) {
                    const int i = lane + ii * 32;      // 0..127 within half-row
                    ulonglong2 e0 = cur0[i], e1 = cur1[i];
                    ulonglong2 a0 = acts[abase + i];
                    FMA2(d00,e0.x,a0.x,d00); FMA2(d00,e0.y,a0.y,d00);
                    FMA2(d10,e1.x,a0.x,d10); FMA2(d10,e1.y,a0.y,d10);
                    ulonglong2 a1 = acts[abase + i + 256];
                    FMA2(d01,e0.x,a1.x,d01); FMA2(d01,e0.y,a1.y,d01);
                    FMA2(d11,e1.x,a1.x,d11); FMA2(d11,e1.y,a1.y,d11);
                    ulonglong2 a2 = acts[abase + i + 512];
                    FMA2(d02,e0.x,a2.x,d02); FMA2(d02,e0.y,a2.y,d02);
                    FMA2(d12,e1.x,a2.x,d12); FMA2(d12,e1.y,a2.y,d12);
                    ulonglong2 a3 = acts[abase + i + 768];
                    FMA2(d03,e0.x,a3.x,d03); FMA2(d03,e0.y,a3.y,d03);
                    FMA2(d13,e1.x,a3.x,d13); FMA2(d13,e1.y,a3.y,d13);
                    FMA2(n0 ,e0.x,e0.x,n0 ); FMA2(n0 ,e0.y,e0.y,n0 );
                    FMA2(n1 ,e1.x,e1.x,n1 ); FMA2(n1 ,e1.y,e1.y,n1 );
                }

                // refill: chunks 2q+4, 2q+5 replace the two just consumed
                {
                    const int c4 = 2*q + 4, c5 = 2*q + 5;
                    if (c4 < 16)
                        issue_chunk(sbuf0 + (unsigned)((c4 % 5) * 2048),
                                    rowbase + chunk_src_off(c4), lane);
                    if (c5 < 16)
                        issue_chunk(sbuf0 + (unsigned)((c5 % 5) * 2048),
                                    rowbase + chunk_src_off(c5), lane);
                }
            }

            float v0,v1,v2,v3,v4,v5,v6,v7,v8,v9;
            { float lo,hi; UNPACK2(lo,hi,d00); v0=lo+hi; }
            { float lo,hi; UNPACK2(lo,hi,d01); v1=lo+hi; }
            { float lo,hi; UNPACK2(lo,hi,d02); v2=lo+hi; }
            { float lo,hi; UNPACK2(lo,hi,d03); v3=lo+hi; }
            { float lo,hi; UNPACK2(lo,hi,n0 ); v4=lo+hi; }
            { float lo,hi; UNPACK2(lo,hi,d10); v5=lo+hi; }
            { float lo,hi; UNPACK2(lo,hi,d11); v6=lo+hi; }
            { float lo,hi; UNPACK2(lo,hi,d12); v7=lo+hi; }
            { float lo,hi; UNPACK2(lo,hi,d13); v8=lo+hi; }
            { float lo,hi; UNPACK2(lo,hi,n1 ); v9=lo+hi; }
            #pragma unroll
            for (int off = 16; off; off >>= 1) {
                v0 += __shfl_down_sync(0xffffffffu, v0, off);
                v1 += __shfl_down_sync(0xffffffffu, v1, off);
                v2 += __shfl_down_sync(0xffffffffu, v2, off);
                v3 += __shfl_down_sync(0xffffffffu, v3, off);
                v4 += __shfl_down_sync(0xffffffffu, v4, off);
                v5 += __shfl_down_sync(0xffffffffu, v5, off);
                v6 += __shfl_down_sync(0xffffffffu, v6, off);
                v7 += __shfl_down_sync(0xffffffffu, v7, off);
                v8 += __shfl_down_sync(0xffffffffu, v8, off);
                v9 += __shfl_down_sync(0xffffffffu, v9, off);
            }
            if (lane == 0) {
                const int j0 = w * 8 + 2*p;
                s_dot[0][j0]   = v0; s_dot[1][j0]   = v1;
                s_dot[2][j0]   = v2; s_dot[3][j0]   = v3; s_norm[j0]   = v4;
                s_dot[0][j0+1] = v5; s_dot[1][j0+1] = v6;
                s_dot[2][j0+1] = v7; s_dot[3][j0+1] = v8; s_norm[j0+1] = v9;
            }
        }
    }
    __syncthreads();

    // ---------------- Phase D (warp-parallel) ----------------
    if (tid < 64) {
        s_rn[tid] = 1.0f / fmaxf(sqrtf(s_norm[tid]), 1e-12f);
        const float p   = s_pred[tid];
        const int   lab = s_lab[tid];
        s_bce[tid] = lab ? logf(p) : log1pf(-p);
        s_pl[tid]  = lab ? p : 0.0f;
    }

    // network + spatial: each warp does 8 rows of conn / Dist (L2-resident)
    {
        const float pl0 = s_pred[lane],        pl1 = s_pred[lane + 32];
        const float ml0 = (pl0 > 0.5f) ? 1.0f : 0.0f;
        const float ml1 = (pl1 > 0.5f) ? 1.0f : 0.0f;
        #pragma unroll
        for (int rr = 0; rr < 8; ++rr) {
            const int r = w * 8 + rr;
            float t1 = fmaf(conn[r*64 + lane],   pl0, conn[r*64 + 32 + lane]   * pl1);
            float t2 = fmaf(g_dist[r][lane],     ml0, g_dist[r][lane + 32]     * ml1);
            #pragma unroll
            for (int off = 16; off; off >>= 1) {
                t1 += __shfl_down_sync(0xffffffffu, t1, off);
                t2 += __shfl_down_sync(0xffffffffu, t2, off);
            }
            if (lane == 0) {
                s_nw[r] = t1 * s_pred[r];
                s_sp[r] = t2 * ((s_pred[r] > 0.5f) ? 1.0f : 0.0f);
            }
        }
    }
    __syncthreads();

    // contrastive: 12 pairs in warp 0
    float ce = 0.0f;
    if (tid < 12) {
        const int p  = tid;
        const int k  = p / 3;
        const int jo = p % 3;
        const int col = jo + (jo >= k ? 1 : 0);
        const int ck = s_act[k];
        const int cj = s_act[col];
        const float rk = s_rn[ck];
        const float l0 = s_dot[k][cj] * rk * s_rn[cj] * INV_TEMP;
        const int base = 20 * jo;
        float mx = l0;
        #pragma unroll
        for (int n = 0; n < 20; ++n) {
            int c = s_inact[base + n];
            float vv = s_dot[k][c] * rk * s_rn[c] * INV_TEMP;
            mx = fmaxf(mx, vv);
        }
        float ssum = expf(l0 - mx);
        #pragma unroll
        for (int n = 0; n < 20; ++n) {
            int c = s_inact[base + n];
            float vv = s_dot[k][c] * rk * s_rn[c] * INV_TEMP;
            ssum += expf(vv - mx);
        }
        ce = logf(ssum) + mx - l0;
    }
    if (tid < 32) {
        #pragma unroll
        for (int off = 16; off; off >>= 1) ce += __shfl_down_sync(0xffffffffu, ce, off);
    }

    if (tid < 32) {
        float r_bce = s_bce[tid] + s_bce[tid+32];
        float r_pl  = s_pl [tid] + s_pl [tid+32];
        float r_p   = s_pred[tid] + s_pred[tid+32];
        float r_lab = (float)s_lab[tid] + (float)s_lab[tid+32];
        float r_sp  = s_sp[tid] + s_sp[tid+32];
        float r_nw  = s_nw[tid] + s_nw[tid+32];
        float pm0 = (s_pred[tid] > 0.5f) ? 1.0f : 0.0f;
        float pm1 = (s_pred[tid+32] > 0.5f) ? 1.0f : 0.0f;
        float r_m = pm0 + pm1;
        #pragma unroll
        for (int off = 16; off; off >>= 1) {
            r_bce += __shfl_down_sync(0xffffffffu, r_bce, off);
            r_pl  += __shfl_down_sync(0xffffffffu, r_pl , off);
            r_p   += __shfl_down_sync(0xffffffffu, r_p  , off);
            r_lab += __shfl_down_sync(0xffffffffu, r_lab, off);
            r_sp  += __shfl_down_sync(0xffffffffu, r_sp , off);
            r_nw  += __shfl_down_sync(0xffffffffu, r_nw , off);
            r_m   += __shfl_down_sync(0xffffffffu, r_m  , off);
        }
        if (tid == 0) {
            float score_b    = -r_bce * (1.0f/64.0f);
            float act_mean   = r_pl / r_lab;
            float inact_mean = (r_p - r_pl) / (64.0f - r_lab);
            float margin_b   = fmaxf(MARGIN_C - (act_mean - inact_mean), 0.0f);
            float contr_b    = ce * (1.0f/12.0f);
            float nm         = r_m;
            float spatial_b  = (nm >= 2.0f) ? r_sp / fmaxf(nm*(nm-1.0f), 1.0f) : 0.0f;
            float net_b      = -r_nw * (1.0f/4096.0f);
            g_partial[b] = 3.0f*score_b + 1.0f*margin_b + 2.0f*s_topk
                         + 1.0f*contr_b + 0.5f*spatial_b + 0.5f*net_b;
        }
    }

    // ---------------- fused final reduction (last block) ----------------
    if (tid == 0) {
        __threadfence();
        unsigned int v = atomicAdd(&g_count, 1u);
        s_islast = (v == (unsigned)(B_SZ - 1));
    }
    __syncthreads();
    if (s_islast) {
        float s = 0.0f;
        for (int i = tid; i < B_SZ; i += 256) s += g_partial[i];
        s_red[tid] = s;
        __syncthreads();
        for (int o = 128; o > 0; o >>= 1) {
            if (tid < o) s_red[tid] += s_red[tid + o];
            __syncthreads();
        }
        if (tid == 0) { out[0] = s_red[0] * (1.0f / (float)B_SZ); g_count = 0; }
    }
}

extern "C" void kernel_launch(void* const* d_in, const int* in_sizes, int n_in,
                              void* d_out, int out_size)
{
    const float* pred = (const float*)d_in[0];
    const int*   lab  = (const int*)  d_in[1];
    const float* emb  = (const float*)d_in[2];
    const float* cpos = (const float*)d_in[3];
    const float* conn = (const float*)d_in[4];
    static int attr_done = 0;
    if (!attr_done) {
        cudaFuncSetAttribute(loss_kernel,
                             cudaFuncAttributeMaxDynamicSharedMemorySize, DYN_SMEM);
        attr_done = 1;
    }
    dist_kernel<<<1, 256>>>(cpos);
    loss_kernel<<<B_SZ, 256, DYN_SMEM>>>(pred, lab, emb, conn, (float*)d_out);
}